// round 1
// baseline (speedup 1.0000x reference)
#include <cuda_runtime.h>
#include <math.h>

#define CH 384
#define RR 32
#define S 32768          // 32^3
#define P 34
#define SP 39304         // 34^3
#define PP 1156          // 34^2
#define BATCH 2
#define NPART 1024

// ---- scratch (alloc-free rule: __device__ globals) ----
__device__ float  g_buf[BATCH * CH * S];     // ~100.7 MB, reused (y1, then branch sum)
__device__ float  g_pad[BATCH * CH * SP];    // ~120.8 MB padded gelu(gn1(conv1)) activation
__device__ float2 g_part[BATCH * NPART];
__device__ float  g_stats[2 * BATCH];        // (mean, rstd) per batch
__device__ float  g_cvec[CH];                // folded bias for final conv

__device__ __forceinline__ float gelu_f(float x) {
    return 0.5f * x * (1.0f + erff(x * 0.70710678118654752f));
}

// ================= SGEMM: Out[b,m,n] = sum_k A'[m,k] * X'[b,k,n] (+bias, epilogue) =====
// A: (384,384) row-major, optionally scaled per-k by wscale (GN2 gamma fold).
// X: either dense (axis<0): row stride xRowStride, n contiguous, optionally (v-mean)*rstd;
//    or padded-shift (axis in {2,3,4}): 34^3 padded layout, per-channel shift offset.
// mode: 0 = write acc+bias ; 1 = write gelu(acc+bias) ; 2 = Out += gelu(acc+bias)
#define BM 128
#define BN 128
#define BK 8
#define TM 8
#define TN 8

__global__ __launch_bounds__(256, 2)
void gemm_kernel(const float* __restrict__ A, const float* __restrict__ X,
                 float* __restrict__ Out,
                 const float* __restrict__ bias,
                 const float* __restrict__ wscale,
                 const float* __restrict__ stats,
                 int axis, long xBatchStride, long xRowStride, int mode)
{
    __shared__ float As[BK][BM];
    __shared__ float Bs[BK][BN];

    const int bz = blockIdx.z;
    const int m0 = blockIdx.y * BM;
    const int n0 = blockIdx.x * BN;
    const float* Xb = X + (long)bz * xBatchStride;
    float mean = 0.f, rstd = 1.f;
    if (stats) { mean = stats[2 * bz]; rstd = stats[2 * bz + 1]; }

    const int tid = threadIdx.x;
    const int ar  = tid >> 1;          // A tile: m row 0..127
    const int ac  = (tid & 1) * 4;     // A tile: k col 0 or 4
    const int bkr = tid >> 5;          // B tile: k row 0..7
    const int bnc = (tid & 31) * 4;    // B tile: n col (x4)
    const int tx  = tid & 15;
    const int ty  = tid >> 4;

    float acc[TM][TN];
    #pragma unroll
    for (int i = 0; i < TM; i++)
        #pragma unroll
        for (int j = 0; j < TN; j++) acc[i][j] = 0.f;

    for (int kt = 0; kt < CH; kt += BK) {
        // ---- load A tile (transposed into As[k][m]) ----
        {
            float4 av = *reinterpret_cast<const float4*>(A + (long)(m0 + ar) * CH + kt + ac);
            if (wscale) {
                av.x *= wscale[kt + ac + 0];
                av.y *= wscale[kt + ac + 1];
                av.z *= wscale[kt + ac + 2];
                av.w *= wscale[kt + ac + 3];
            }
            As[ac + 0][ar] = av.x;
            As[ac + 1][ar] = av.y;
            As[ac + 2][ar] = av.z;
            As[ac + 3][ar] = av.w;
        }
        // ---- load B tile ----
        {
            const int kk = kt + bkr;
            if (axis < 0) {
                float4 xv = *reinterpret_cast<const float4*>(Xb + (long)kk * xRowStride + n0 + bnc);
                if (stats) {
                    xv.x = (xv.x - mean) * rstd; xv.y = (xv.y - mean) * rstd;
                    xv.z = (xv.z - mean) * rstd; xv.w = (xv.w - mean) * rstd;
                }
                Bs[bkr][bnc + 0] = xv.x; Bs[bkr][bnc + 1] = xv.y;
                Bs[bkr][bnc + 2] = xv.z; Bs[bkr][bnc + 3] = xv.w;
            } else {
                // fused axial shift: per-channel offset into padded 34^3 layout
                const int n = n0 + bnc;
                const int d = n >> 10, h = (n >> 5) & 31, w = n & 31;
                const int sh = 2 - (kk >> 7);           // chunk 0/1/2 -> offset 2/1/0
                int od = 1, oh = 1, ow = 1;
                if      (axis == 2) od = sh;
                else if (axis == 3) oh = sh;
                else                ow = sh;
                const float* p = Xb + (long)kk * SP + (d + od) * PP + (h + oh) * P + (w + ow);
                Bs[bkr][bnc + 0] = p[0]; Bs[bkr][bnc + 1] = p[1];
                Bs[bkr][bnc + 2] = p[2]; Bs[bkr][bnc + 3] = p[3];
            }
        }
        __syncthreads();

        #pragma unroll
        for (int k = 0; k < BK; k++) {
            float a[TM], b[TN];
            float4 a0 = *reinterpret_cast<const float4*>(&As[k][ty * TM]);
            float4 a1 = *reinterpret_cast<const float4*>(&As[k][ty * TM + 4]);
            float4 b0 = *reinterpret_cast<const float4*>(&Bs[k][tx * TN]);
            float4 b1 = *reinterpret_cast<const float4*>(&Bs[k][tx * TN + 4]);
            a[0]=a0.x; a[1]=a0.y; a[2]=a0.z; a[3]=a0.w;
            a[4]=a1.x; a[5]=a1.y; a[6]=a1.z; a[7]=a1.w;
            b[0]=b0.x; b[1]=b0.y; b[2]=b0.z; b[3]=b0.w;
            b[4]=b1.x; b[5]=b1.y; b[6]=b1.z; b[7]=b1.w;
            #pragma unroll
            for (int i = 0; i < TM; i++)
                #pragma unroll
                for (int j = 0; j < TN; j++)
                    acc[i][j] = fmaf(a[i], b[j], acc[i][j]);
        }
        __syncthreads();
    }

    // ---- epilogue ----
    #pragma unroll
    for (int i = 0; i < TM; i++) {
        const int m = m0 + ty * TM + i;
        const float bv = bias[m];
        #pragma unroll
        for (int j = 0; j < TN; j++) {
            const int n = n0 + tx * TN + j;
            float v = acc[i][j] + bv;
            if (mode >= 1) v = gelu_f(v);
            const long oi = (long)bz * ((long)CH * S) + (long)m * S + n;
            if (mode == 2) v += Out[oi];
            Out[oi] = v;
        }
    }
}

// ================= GroupNorm(1) reduction, two-stage =================
__global__ void reduce_stage1(const float* __restrict__ buf)
{
    const int b = blockIdx.y;
    const float4* p4 = reinterpret_cast<const float4*>(buf + (long)b * CH * S);
    const long total4 = ((long)CH * S) / 4;
    float s = 0.f, ss = 0.f;
    for (long i = (long)blockIdx.x * blockDim.x + threadIdx.x; i < total4;
         i += (long)gridDim.x * blockDim.x) {
        float4 v = p4[i];
        s  += v.x + v.y + v.z + v.w;
        ss  = fmaf(v.x, v.x, ss); ss = fmaf(v.y, v.y, ss);
        ss  = fmaf(v.z, v.z, ss); ss = fmaf(v.w, v.w, ss);
    }
    __shared__ float sh1[256], sh2[256];
    sh1[threadIdx.x] = s; sh2[threadIdx.x] = ss;
    __syncthreads();
    for (int st = 128; st > 0; st >>= 1) {
        if (threadIdx.x < st) {
            sh1[threadIdx.x] += sh1[threadIdx.x + st];
            sh2[threadIdx.x] += sh2[threadIdx.x + st];
        }
        __syncthreads();
    }
    if (threadIdx.x == 0)
        g_part[b * NPART + blockIdx.x] = make_float2(sh1[0], sh2[0]);
}

__global__ void reduce_stage2()
{
    const int b = blockIdx.x;
    double s = 0.0, ss = 0.0;
    for (int i = threadIdx.x; i < NPART; i += blockDim.x) {
        float2 v = g_part[b * NPART + i];
        s += (double)v.x; ss += (double)v.y;
    }
    __shared__ double d1[256], d2[256];
    d1[threadIdx.x] = s; d2[threadIdx.x] = ss;
    __syncthreads();
    for (int st = 128; st > 0; st >>= 1) {
        if (threadIdx.x < st) {
            d1[threadIdx.x] += d1[threadIdx.x + st];
            d2[threadIdx.x] += d2[threadIdx.x + st];
        }
        __syncthreads();
    }
    if (threadIdx.x == 0) {
        const double total = (double)CH * (double)S;
        const double mean  = d1[0] / total;
        const double var   = d2[0] / total - mean * mean;
        g_stats[2 * b]     = (float)mean;
        g_stats[2 * b + 1] = (float)(1.0 / sqrt(var + 1e-5));
    }
}

// ====== GN1 affine + GELU + write into zero-padded 34^3 buffer (halo = 0) ======
__global__ void gn_gelu_pad_kernel(const float* __restrict__ buf,
                                   const float* __restrict__ g1,
                                   const float* __restrict__ bt1)
{
    const long idx = (long)blockIdx.x * blockDim.x + threadIdx.x;
    if (idx >= (long)BATCH * CH * SP) return;
    const int sp = (int)(idx % SP);
    const int bc = (int)(idx / SP);
    const int pd = sp / PP;
    const int r  = sp - pd * PP;
    const int ph = r / P;
    const int pw = r - ph * P;
    float v = 0.f;
    if (pd >= 1 && pd <= RR && ph >= 1 && ph <= RR && pw >= 1 && pw <= RR) {
        const int c = bc % CH;
        const int b = bc / CH;
        const long si = (long)bc * S + (pd - 1) * 1024 + (ph - 1) * RR + (pw - 1);
        float t = buf[si];
        t = (t - g_stats[2 * b]) * g_stats[2 * b + 1] * g1[c] + bt1[c];
        v = gelu_f(t);
    }
    g_pad[idx] = v;
}

// ====== fold bt2 + b3 into effective bias for final conv: cvec[o] = b3[o] + sum_c w3[o,c]*bt2[c]
__global__ void cvec_kernel(const float* __restrict__ w3,
                            const float* __restrict__ bt2,
                            const float* __restrict__ b3)
{
    const int o = blockIdx.x * blockDim.x + threadIdx.x;
    if (o >= CH) return;
    float s = b3[o];
    for (int c = 0; c < CH; c++) s = fmaf(w3[o * CH + c], bt2[c], s);
    g_cvec[o] = s;
}

extern "C" void kernel_launch(void* const* d_in, const int* in_sizes, int n_in,
                              void* d_out, int out_size)
{
    const float* x   = (const float*)d_in[0];
    const float* w1  = (const float*)d_in[1];
    const float* b1  = (const float*)d_in[2];
    const float* g1  = (const float*)d_in[3];
    const float* bt1 = (const float*)d_in[4];
    const float* w21 = (const float*)d_in[5];
    const float* b21 = (const float*)d_in[6];
    const float* w22 = (const float*)d_in[7];
    const float* b22 = (const float*)d_in[8];
    const float* w23 = (const float*)d_in[9];
    const float* b23 = (const float*)d_in[10];
    const float* g2  = (const float*)d_in[11];
    const float* bt2 = (const float*)d_in[12];
    const float* w3  = (const float*)d_in[13];
    const float* b3  = (const float*)d_in[14];
    float* out = (float*)d_out;

    float* buf;   cudaGetSymbolAddress((void**)&buf,   g_buf);
    float* pad;   cudaGetSymbolAddress((void**)&pad,   g_pad);
    float* cvec;  cudaGetSymbolAddress((void**)&cvec,  g_cvec);
    float* stats; cudaGetSymbolAddress((void**)&stats, g_stats);

    const dim3 gg(S / BN, CH / BM, BATCH);   // (256, 3, 2)

    // 1) conv1: y1 = W1 x + b1
    gemm_kernel<<<gg, 256>>>(w1, x, buf, b1, nullptr, nullptr, -1,
                             (long)CH * S, (long)S, 0);
    // 2) GN1 stats over (C,D,H,W) per sample
    reduce_stage1<<<dim3(NPART, BATCH), 256>>>(buf);
    reduce_stage2<<<BATCH, 256>>>();
    // 3) GN1 affine + GELU + zero-pad into 34^3 buffer
    {
        const long tot = (long)BATCH * CH * SP;
        gn_gelu_pad_kernel<<<(unsigned)((tot + 255) / 256), 256>>>(buf, g1, bt1);
    }
    // 4) three shift-conv branches, GELU, summed into buf (shift fused in GEMM loader)
    gemm_kernel<<<gg, 256>>>(w21, pad, buf, b21, nullptr, nullptr, 3,
                             (long)CH * SP, (long)SP, 1);   // x_lr (axis 3)
    gemm_kernel<<<gg, 256>>>(w22, pad, buf, b22, nullptr, nullptr, 2,
                             (long)CH * SP, (long)SP, 2);   // x_td (axis 2)
    gemm_kernel<<<gg, 256>>>(w23, pad, buf, b23, nullptr, nullptr, 4,
                             (long)CH * SP, (long)SP, 2);   // x_hd (axis 4)
    // 5) GN2 stats
    reduce_stage1<<<dim3(NPART, BATCH), 256>>>(buf);
    reduce_stage2<<<BATCH, 256>>>();
    // 6) fold bt2/b3; final conv with GN2 folded (A *= g2[c], X -> (X-mean)*rstd)
    cvec_kernel<<<2, 192>>>(w3, bt2, b3);
    gemm_kernel<<<gg, 256>>>(w3, buf, out, cvec, g2, stats, -1,
                             (long)CH * S, (long)S, 0);
}

// round 4
// speedup vs baseline: 2.1975x; 2.1975x over previous
#include <cuda_runtime.h>
#include <cuda_bf16.h>
#include <math.h>
#include <stdint.h>

#define CH 384
#define RR 32
#define S 32768             // 32^3
#define P 34
#define PP 1156             // 34^2
#define SPP 39304           // 34^3
#define BATCH 2
#define NPART 1024
#define KPRIME 1152         // 3*384 bf16x3 folded K
#define NSTAGE 18           // KPRIME / 64
#define AP_ELE (CH * KPRIME)

// smem geometry (bytes)
#define A_STRIDE 144        // (64+8) bf16 per row
#define B_STRIDE 272        // (128+8) bf16 per row
#define A_BYTES  (128 * A_STRIDE)   // 18432
#define B_BYTES  (64 * B_STRIDE)    // 17408
#define STAGE_BYTES (A_BYTES + B_BYTES)  // 35840

// ---------------- scratch (__device__ globals; alloc-free rule) ----------------
__device__ __align__(16) float    g_buf[BATCH * CH * S];            // fp32 activations
__device__ __align__(16) unsigned short g_hi16 [BATCH * CH * S];    // dense hi plane
__device__ __align__(16) unsigned short g_lo16 [BATCH * CH * S];    // dense lo plane
__device__ __align__(16) unsigned short g_phi16[BATCH * CH * SPP];  // padded hi plane
__device__ __align__(16) unsigned short g_plo16[BATCH * CH * SPP];  // padded lo plane
__device__ __align__(16) unsigned short g_apack[5 * AP_ELE];        // packed bf16x3 weights
__device__ float2 g_part[BATCH * NPART];
__device__ float  g_stats[2 * BATCH];
__device__ float  g_cvec[CH];

__device__ __forceinline__ float gelu_f(float x) {
    return 0.5f * x * (1.0f + erff(x * 0.70710678118654752f));
}

// ---------------- PTX helpers (compute_80-compatible) ----------------
__device__ __forceinline__ uint32_t smem_u32(const void* p) {
    uint32_t a;
    asm("{ .reg .u64 t; cvta.to.shared.u64 t, %1; cvt.u32.u64 %0, t; }" : "=r"(a) : "l"(p));
    return a;
}
__device__ __forceinline__ void cp16(uint32_t dst, const void* src) {
    asm volatile("cp.async.cg.shared.global [%0], [%1], 16;" :: "r"(dst), "l"(src));
}
__device__ __forceinline__ void cp4(uint32_t dst, const void* src) {
    asm volatile("cp.async.ca.shared.global [%0], [%1], 4;" :: "r"(dst), "l"(src));
}
__device__ __forceinline__ void ldsm4(uint32_t* r, uint32_t addr) {
    asm volatile("ldmatrix.sync.aligned.m8n8.x4.shared.b16 {%0,%1,%2,%3}, [%4];"
        : "=r"(r[0]), "=r"(r[1]), "=r"(r[2]), "=r"(r[3]) : "r"(addr));
}
__device__ __forceinline__ void ldsm4t(uint32_t* r, uint32_t addr) {
    asm volatile("ldmatrix.sync.aligned.m8n8.x4.trans.shared.b16 {%0,%1,%2,%3}, [%4];"
        : "=r"(r[0]), "=r"(r[1]), "=r"(r[2]), "=r"(r[3]) : "r"(addr));
}
__device__ __forceinline__ void mma16816(float* c, const uint32_t* a, uint32_t b0, uint32_t b1) {
    asm volatile("mma.sync.aligned.m16n8k16.row.col.f32.bf16.bf16.f32 "
        "{%0,%1,%2,%3}, {%4,%5,%6,%7}, {%8,%9}, {%0,%1,%2,%3};"
        : "+f"(c[0]), "+f"(c[1]), "+f"(c[2]), "+f"(c[3])
        : "r"(a[0]), "r"(a[1]), "r"(a[2]), "r"(a[3]), "r"(b0), "r"(b1));
}

// =====================================================================
// HMMA bf16x3 GEMM: Out[b,m,n] = sum_{k'} A'[m,k'] * B'[n,k']
//   A' : packed [384][1152] bf16  ([hi(384) | lo(384) | hi(384)])
//   B' : stage c<12 -> hi plane, else lo plane; channel = (c%6)*64 + k
//   axis <0: dense plane [b][ch][S]; axis in {2,3,4}: padded plane + shift
//   mode: 0 write acc+bias ; 1 write gelu(acc+bias) ; 2 Out += gelu(acc+bias)
// =====================================================================
__device__ __forceinline__ void load_stage(
    char* smem, uint32_t sb, int c, int tid, int b, int m0, int n0, int axis,
    const unsigned short* __restrict__ apack,
    const unsigned short* __restrict__ hiP,
    const unsigned short* __restrict__ loP)
{
    const uint32_t stOff = (uint32_t)(c & 1) * STAGE_BYTES;
    const uint32_t aBase = sb + stOff;
    const uint32_t bBase = aBase + A_BYTES;
    // ---- A: 128 rows x 64 bf16 (cp.async 16B, always aligned) ----
    const unsigned short* ag = apack + (long)m0 * KPRIME + c * 64;
    #pragma unroll
    for (int it = 0; it < 4; it++) {
        const int flat = it * 256 + tid;    // 0..1023
        const int m = flat >> 3, g = flat & 7;
        cp16(aBase + m * A_STRIDE + g * 16, ag + (long)m * KPRIME + g * 8);
    }
    const int kbase = (c % 6) * 64;
    const unsigned short* plane = (c < 12) ? hiP : loP;
    if (axis < 0) {
        // ---- dense B: cp.async 4B (element offsets even -> aligned) ----
        #pragma unroll
        for (int it = 0; it < 16; it++) {
            const int flat = it * 256 + tid;    // 0..4095
            const int k = flat >> 6, ni2 = flat & 63;
            cp4(bBase + k * B_STRIDE + ni2 * 4,
                plane + ((long)b * CH + kbase + k) * (long)S + n0 + 2 * ni2);
        }
    } else {
        // ---- shifted B:可能 2B-aligned sources -> plain u16 loads ----
        #pragma unroll
        for (int it = 0; it < 16; it++) {
            const int flat = it * 256 + tid;    // 0..4095
            const int k = flat >> 6, ni2 = flat & 63;
            const int ch = kbase + k;
            const int n = n0 + 2 * ni2;
            const int d = n >> 10, h = (n >> 5) & 31, w = n & 31;
            const int sh = 2 - (ch >> 7);
            int od = 1, oh = 1, ow = 1;
            if      (axis == 2) od = sh;
            else if (axis == 3) oh = sh;
            else                ow = sh;
            const unsigned short* src = plane + ((long)b * CH + ch) * (long)SPP
                        + (d + od) * PP + (h + oh) * P + (w + ow);
            const uint32_t v = (uint32_t)src[0] | ((uint32_t)src[1] << 16);
            *reinterpret_cast<uint32_t*>(smem + stOff + A_BYTES + k * B_STRIDE + ni2 * 4) = v;
        }
    }
    asm volatile("cp.async.commit_group;" ::: "memory");
}

__global__ __launch_bounds__(256, 2)
void gemm_tc(const unsigned short* __restrict__ apack,
             const unsigned short* __restrict__ hiP,
             const unsigned short* __restrict__ loP,
             float* __restrict__ Out, const float* __restrict__ bias,
             int axis, int mode)
{
    extern __shared__ char smem[];
    const uint32_t sb = smem_u32(smem);
    const int tid = threadIdx.x, wid = tid >> 5, lane = tid & 31;
    const int m0 = blockIdx.x * 128;
    const int n0 = blockIdx.y * 128;
    const int b  = blockIdx.z;
    const int wm = (wid & 1) * 64;       // warp m offset in CTA tile
    const int wn = (wid >> 1) * 32;      // warp n offset

    float acc[4][4][4];
    #pragma unroll
    for (int i = 0; i < 4; i++)
        #pragma unroll
        for (int j = 0; j < 4; j++)
            #pragma unroll
            for (int k = 0; k < 4; k++) acc[i][j][k] = 0.f;

    load_stage(smem, sb, 0, tid, b, m0, n0, axis, apack, hiP, loP);

    for (int c = 0; c < NSTAGE; c++) {
        if (c + 1 < NSTAGE) {
            load_stage(smem, sb, c + 1, tid, b, m0, n0, axis, apack, hiP, loP);
            asm volatile("cp.async.wait_group 1;" ::: "memory");
        } else {
            asm volatile("cp.async.wait_group 0;" ::: "memory");
        }
        __syncthreads();

        const uint32_t aBase = sb + (uint32_t)(c & 1) * STAGE_BYTES;
        const uint32_t bBase = aBase + A_BYTES;
        #pragma unroll
        for (int ks = 0; ks < 4; ks++) {
            const int k0 = ks * 16;
            uint32_t afr[4][4], bfr[2][4];
            #pragma unroll
            for (int mt = 0; mt < 4; mt++)
                ldsm4(afr[mt], aBase + (wm + mt * 16 + (lane & 15)) * A_STRIDE
                               + (k0 + (lane >> 4) * 8) * 2);
            #pragma unroll
            for (int nt = 0; nt < 2; nt++)
                ldsm4t(bfr[nt], bBase + (k0 + (lane & 15)) * B_STRIDE
                                + (wn + nt * 16 + (lane >> 4) * 8) * 2);
            #pragma unroll
            for (int mt = 0; mt < 4; mt++)
                #pragma unroll
                for (int n8 = 0; n8 < 4; n8++)
                    mma16816(acc[mt][n8], afr[mt],
                             bfr[n8 >> 1][(n8 & 1) * 2],
                             bfr[n8 >> 1][(n8 & 1) * 2 + 1]);
        }
        __syncthreads();
    }

    // ---- epilogue ----
    const int g = lane >> 2, t = lane & 3;
    #pragma unroll
    for (int mt = 0; mt < 4; mt++) {
        #pragma unroll
        for (int half = 0; half < 2; half++) {
            const int m = m0 + wm + mt * 16 + g + half * 8;
            const float bv = bias[m];
            float* op = Out + ((long)b * CH + m) * (long)S + n0 + wn;
            #pragma unroll
            for (int n8 = 0; n8 < 4; n8++) {
                float2 v;
                v.x = acc[mt][n8][half * 2]     + bv;
                v.y = acc[mt][n8][half * 2 + 1] + bv;
                if (mode >= 1) { v.x = gelu_f(v.x); v.y = gelu_f(v.y); }
                float* dst = op + n8 * 8 + 2 * t;
                if (mode == 2) {
                    float2 o = *reinterpret_cast<const float2*>(dst);
                    v.x += o.x; v.y += o.y;
                }
                *reinterpret_cast<float2*>(dst) = v;
            }
        }
    }
}

// ============ split helpers ============
__device__ __forceinline__ void split_one(float v, unsigned short& hi, unsigned short& lo) {
    const __nv_bfloat16 h = __float2bfloat16_rn(v);
    const __nv_bfloat16 l = __float2bfloat16_rn(v - __bfloat162float(h));
    hi = __bfloat16_as_ushort(h);
    lo = __bfloat16_as_ushort(l);
}
__device__ __forceinline__ void split_pack2(float v0, float v1, uint32_t& hi, uint32_t& lo) {
    unsigned short h0, l0, h1, l1;
    split_one(v0, h0, l0); split_one(v1, h1, l1);
    hi = ((uint32_t)h1 << 16) | h0;
    lo = ((uint32_t)l1 << 16) | l0;
}

// ============ pack weights: [mat][m][ hi(384) | lo(384) | hi(384) ] ============
__global__ void apack_prep(const float* __restrict__ w1, const float* __restrict__ w21,
                           const float* __restrict__ w22, const float* __restrict__ w23,
                           const float* __restrict__ w3, const float* __restrict__ g2)
{
    const int idx = blockIdx.x * blockDim.x + threadIdx.x;
    if (idx >= 5 * CH * CH) return;
    const int mat = idx / (CH * CH);
    const int rem = idx % (CH * CH);
    const int m = rem / CH, k = rem % CH;
    const float* W = (mat == 0) ? w1 : (mat == 1) ? w21 : (mat == 2) ? w22
                   : (mat == 3) ? w23 : w3;
    float v = W[m * CH + k];
    if (mat == 4) v *= g2[k];
    unsigned short hi, lo;
    split_one(v, hi, lo);
    const long base = (long)mat * AP_ELE + (long)m * KPRIME;
    g_apack[base + k]           = hi;
    g_apack[base + CH + k]      = lo;
    g_apack[base + 2 * CH + k]  = hi;
}

// ============ convert raw x -> dense hi/lo planes (2 elems/thread) ============
__global__ void convert_x(const float* __restrict__ x)
{
    const long i = (long)blockIdx.x * blockDim.x + threadIdx.x;   // u32 pair index
    const long tot2 = (long)BATCH * CH * S / 2;
    if (i >= tot2) return;
    const float2 v = reinterpret_cast<const float2*>(x)[i];
    uint32_t hi, lo; split_pack2(v.x, v.y, hi, lo);
    reinterpret_cast<uint32_t*>(g_hi16)[i] = hi;
    reinterpret_cast<uint32_t*>(g_lo16)[i] = lo;
}

// ============ branch-sum -> normalized dense hi/lo planes (GN2 fold) ============
__global__ void convert_norm()
{
    const long i = (long)blockIdx.x * blockDim.x + threadIdx.x;
    const long tot2 = (long)BATCH * CH * S / 2;
    if (i >= tot2) return;
    const int b = (int)(i / ((long)CH * S / 2));
    const float mean = g_stats[2 * b], rstd = g_stats[2 * b + 1];
    const float2 v = reinterpret_cast<const float2*>(g_buf)[i];
    uint32_t hi, lo;
    split_pack2((v.x - mean) * rstd, (v.y - mean) * rstd, hi, lo);
    reinterpret_cast<uint32_t*>(g_hi16)[i] = hi;
    reinterpret_cast<uint32_t*>(g_lo16)[i] = lo;
}

// ============ GN1 affine + GELU -> zero-padded 34^3 hi/lo planes ============
__global__ void pad_split(const float* __restrict__ g1, const float* __restrict__ bt1)
{
    const long i = (long)blockIdx.x * blockDim.x + threadIdx.x;
    if (i >= (long)BATCH * CH * SPP) return;
    const int b  = (int)(i / ((long)CH * SPP));
    const long r = i - (long)b * CH * SPP;
    const int c  = (int)(r / SPP);
    const int sp = (int)(r - (long)c * SPP);
    const int pd = sp / PP;
    const int r2 = sp - pd * PP;
    const int ph = r2 / P;
    const int pw = r2 - ph * P;
    unsigned short hi = 0, lo = 0;
    if (pd >= 1 && pd <= RR && ph >= 1 && ph <= RR && pw >= 1 && pw <= RR) {
        const int s = (pd - 1) * 1024 + (ph - 1) * RR + (pw - 1);
        float y = g_buf[((long)b * CH + c) * S + s];
        y = gelu_f((y - g_stats[2 * b]) * g_stats[2 * b + 1] * g1[c] + bt1[c]);
        split_one(y, hi, lo);
    }
    g_phi16[i] = hi; g_plo16[i] = lo;
}

// ================= GroupNorm(1) reduction, two-stage =================
__global__ void reduce_stage1(const float* __restrict__ buf)
{
    const int b = blockIdx.y;
    const float4* p4 = reinterpret_cast<const float4*>(buf + (long)b * CH * S);
    const long total4 = ((long)CH * S) / 4;
    float s = 0.f, ss = 0.f;
    for (long i = (long)blockIdx.x * blockDim.x + threadIdx.x; i < total4;
         i += (long)gridDim.x * blockDim.x) {
        float4 v = p4[i];
        s += v.x + v.y + v.z + v.w;
        ss = fmaf(v.x, v.x, ss); ss = fmaf(v.y, v.y, ss);
        ss = fmaf(v.z, v.z, ss); ss = fmaf(v.w, v.w, ss);
    }
    __shared__ float sh1[256], sh2[256];
    sh1[threadIdx.x] = s; sh2[threadIdx.x] = ss;
    __syncthreads();
    for (int st = 128; st > 0; st >>= 1) {
        if (threadIdx.x < st) {
            sh1[threadIdx.x] += sh1[threadIdx.x + st];
            sh2[threadIdx.x] += sh2[threadIdx.x + st];
        }
        __syncthreads();
    }
    if (threadIdx.x == 0)
        g_part[b * NPART + blockIdx.x] = make_float2(sh1[0], sh2[0]);
}

__global__ void reduce_stage2()
{
    const int b = blockIdx.x;
    double s = 0.0, ss = 0.0;
    for (int i = threadIdx.x; i < NPART; i += blockDim.x) {
        float2 v = g_part[b * NPART + i];
        s += (double)v.x; ss += (double)v.y;
    }
    __shared__ double d1[256], d2[256];
    d1[threadIdx.x] = s; d2[threadIdx.x] = ss;
    __syncthreads();
    for (int st = 128; st > 0; st >>= 1) {
        if (threadIdx.x < st) {
            d1[threadIdx.x] += d1[threadIdx.x + st];
            d2[threadIdx.x] += d2[threadIdx.x + st];
        }
        __syncthreads();
    }
    if (threadIdx.x == 0) {
        const double total = (double)CH * (double)S;
        const double mean  = d1[0] / total;
        const double var   = d2[0] / total - mean * mean;
        g_stats[2 * b]     = (float)mean;
        g_stats[2 * b + 1] = (float)(1.0 / sqrt(var + 1e-5));
    }
}

// ====== cvec[o] = b3[o] + sum_c w3[o,c]*bt2[c] ======
__global__ void cvec_kernel(const float* __restrict__ w3,
                            const float* __restrict__ bt2,
                            const float* __restrict__ b3)
{
    const int o = blockIdx.x * blockDim.x + threadIdx.x;
    if (o >= CH) return;
    float s = b3[o];
    for (int c = 0; c < CH; c++) s = fmaf(w3[o * CH + c], bt2[c], s);
    g_cvec[o] = s;
}

extern "C" void kernel_launch(void* const* d_in, const int* in_sizes, int n_in,
                              void* d_out, int out_size)
{
    const float* x   = (const float*)d_in[0];
    const float* w1  = (const float*)d_in[1];
    const float* b1  = (const float*)d_in[2];
    const float* g1  = (const float*)d_in[3];
    const float* bt1 = (const float*)d_in[4];
    const float* w21 = (const float*)d_in[5];
    const float* b21 = (const float*)d_in[6];
    const float* w22 = (const float*)d_in[7];
    const float* b22 = (const float*)d_in[8];
    const float* w23 = (const float*)d_in[9];
    const float* b23 = (const float*)d_in[10];
    const float* g2  = (const float*)d_in[11];
    const float* bt2 = (const float*)d_in[12];
    const float* w3  = (const float*)d_in[13];
    const float* b3  = (const float*)d_in[14];
    float* out = (float*)d_out;

    float*          buf;  cudaGetSymbolAddress((void**)&buf,  g_buf);
    unsigned short* hip;  cudaGetSymbolAddress((void**)&hip,  g_hi16);
    unsigned short* lop;  cudaGetSymbolAddress((void**)&lop,  g_lo16);
    unsigned short* phip; cudaGetSymbolAddress((void**)&phip, g_phi16);
    unsigned short* plop; cudaGetSymbolAddress((void**)&plop, g_plo16);
    unsigned short* apk;  cudaGetSymbolAddress((void**)&apk,  g_apack);
    float*          cvec; cudaGetSymbolAddress((void**)&cvec, g_cvec);

    const int SMEM_GEMM = 2 * STAGE_BYTES;   // 71680
    cudaFuncSetAttribute(gemm_tc, cudaFuncAttributeMaxDynamicSharedMemorySize, SMEM_GEMM);

    const dim3 gg(3, S / 128, BATCH);   // m fastest -> L2 reuse of B across m-tiles

    // 0) pack weights + fold biases
    apack_prep<<<(5 * CH * CH + 255) / 256, 256>>>(w1, w21, w22, w23, w3, g2);
    cvec_kernel<<<2, 192>>>(w3, bt2, b3);
    // 1) x -> hi/lo planes; conv1
    {
        const long tot2 = (long)BATCH * CH * S / 2;
        convert_x<<<(unsigned)((tot2 + 255) / 256), 256>>>(x);
    }
    gemm_tc<<<gg, 256, SMEM_GEMM>>>(apk + 0L * AP_ELE, hip, lop, buf, b1, -1, 0);
    // 2) GN1 stats
    reduce_stage1<<<dim3(NPART, BATCH), 256>>>(buf);
    reduce_stage2<<<BATCH, 256>>>();
    // 3) GN1 affine + GELU + zero-padded hi/lo planes
    {
        const long tot = (long)BATCH * CH * SPP;
        pad_split<<<(unsigned)((tot + 255) / 256), 256>>>(g1, bt1);
    }
    // 4) three shifted branch convs (shift fused in B loader), gelu-summed into buf
    gemm_tc<<<gg, 256, SMEM_GEMM>>>(apk + 1L * AP_ELE, phip, plop, buf, b21, 3, 1);
    gemm_tc<<<gg, 256, SMEM_GEMM>>>(apk + 2L * AP_ELE, phip, plop, buf, b22, 2, 2);
    gemm_tc<<<gg, 256, SMEM_GEMM>>>(apk + 3L * AP_ELE, phip, plop, buf, b23, 4, 2);
    // 5) GN2 stats; normalized planes; final conv (g2 in A, bt2+b3 in cvec)
    reduce_stage1<<<dim3(NPART, BATCH), 256>>>(buf);
    reduce_stage2<<<BATCH, 256>>>();
    {
        const long tot2 = (long)BATCH * CH * S / 2;
        convert_norm<<<(unsigned)((tot2 + 255) / 256), 256>>>();
    }
    gemm_tc<<<gg, 256, SMEM_GEMM>>>(apk + 4L * AP_ELE, hip, lop, out, cvec, -1, 0);
}

// round 7
// speedup vs baseline: 2.2541x; 1.0257x over previous
#include <cuda_runtime.h>
#include <cuda_bf16.h>
#include <math.h>
#include <stdint.h>

#define CH 384
#define RR 32
#define S 32768             // 32^3
#define P 34
#define PP 1156             // 34^2
#define SPP 39304           // 34^3
#define BATCH 2
#define KPRIME 1152         // 3*384 bf16x3 folded K
#define NSTAGE 18           // KPRIME / 64
#define NPIPE 3             // cp.async pipeline depth
#define AP_ELE (CH * KPRIME)

// smem geometry (bytes)
#define A_STRIDE 144        // (64+8) bf16 per row
#define B_STRIDE 272        // (128+8) bf16 per row
#define A_BYTES  (128 * A_STRIDE)   // 18432
#define B_BYTES  (64 * B_STRIDE)    // 17408
#define STAGE_BYTES (A_BYTES + B_BYTES)  // 35840
#define SMEM_GEMM (NPIPE * STAGE_BYTES)  // 107520

// ---------------- scratch (__device__ globals; alloc-free rule) ----------------
__device__ __align__(16) float    g_buf[BATCH * CH * S];            // fp32 activations
__device__ __align__(16) unsigned short g_hi16 [BATCH * CH * S];    // dense hi plane
__device__ __align__(16) unsigned short g_lo16 [BATCH * CH * S];    // dense lo plane
__device__ __align__(16) unsigned short g_phi16[BATCH * CH * SPP];  // padded hi plane
__device__ __align__(16) unsigned short g_plo16[BATCH * CH * SPP];  // padded lo plane
__device__ __align__(16) unsigned short g_apack[5 * AP_ELE];        // packed bf16x3 weights
__device__ float g_acc1[2 * BATCH];     // GN1 (sum, sumsq) atomics
__device__ float g_acc2[2 * BATCH];     // GN2 (sum, sumsq) atomics
__device__ float g_stats1[2 * BATCH];   // GN1 (mean, rstd)
__device__ float g_stats2[2 * BATCH];   // GN2 (mean, rstd)
__device__ float g_cvec[CH];            // b3 + w3·bt2
__device__ float g_wrsum[CH];           // rowsum(w3·g2)

__device__ __forceinline__ float gelu_f(float x) {
    return 0.5f * x * (1.0f + erff(x * 0.70710678118654752f));
}

// ---------------- PTX helpers (compute_80-compatible) ----------------
__device__ __forceinline__ uint32_t smem_u32(const void* p) {
    uint32_t a;
    asm("{ .reg .u64 t; cvta.to.shared.u64 t, %1; cvt.u32.u64 %0, t; }" : "=r"(a) : "l"(p));
    return a;
}
__device__ __forceinline__ void cp16(uint32_t dst, const void* src) {
    asm volatile("cp.async.cg.shared.global [%0], [%1], 16;" :: "r"(dst), "l"(src));
}
__device__ __forceinline__ void cp4(uint32_t dst, const void* src) {
    asm volatile("cp.async.ca.shared.global [%0], [%1], 4;" :: "r"(dst), "l"(src));
}
__device__ __forceinline__ void ldsm4(uint32_t* r, uint32_t addr) {
    asm volatile("ldmatrix.sync.aligned.m8n8.x4.shared.b16 {%0,%1,%2,%3}, [%4];"
        : "=r"(r[0]), "=r"(r[1]), "=r"(r[2]), "=r"(r[3]) : "r"(addr));
}
__device__ __forceinline__ void ldsm4t(uint32_t* r, uint32_t addr) {
    asm volatile("ldmatrix.sync.aligned.m8n8.x4.trans.shared.b16 {%0,%1,%2,%3}, [%4];"
        : "=r"(r[0]), "=r"(r[1]), "=r"(r[2]), "=r"(r[3]) : "r"(addr));
}
__device__ __forceinline__ void mma16816(float* c, const uint32_t* a, uint32_t b0, uint32_t b1) {
    asm volatile("mma.sync.aligned.m16n8k16.row.col.f32.bf16.bf16.f32 "
        "{%0,%1,%2,%3}, {%4,%5,%6,%7}, {%8,%9}, {%0,%1,%2,%3};"
        : "+f"(c[0]), "+f"(c[1]), "+f"(c[2]), "+f"(c[3])
        : "r"(a[0]), "r"(a[1]), "r"(a[2]), "r"(a[3]), "r"(b0), "r"(b1));
}
__device__ __forceinline__ void split_one(float v, unsigned short& hi, unsigned short& lo) {
    const __nv_bfloat16 h = __float2bfloat16_rn(v);
    const __nv_bfloat16 l = __float2bfloat16_rn(v - __bfloat162float(h));
    hi = __bfloat16_as_ushort(h);
    lo = __bfloat16_as_ushort(l);
}

// =====================================================================
// HMMA bf16x3 GEMM. modes:
//  0: write fp32 acc+bias; fused GN1 stats -> g_acc1
//  1: write gelu(acc+bias) fp32
//  2: Out += gelu(acc+bias) fp32
//  3: v = Out + gelu(acc+bias); fused GN2 stats -> g_acc2; write hi/lo planes
//  4: final: v = rstd*acc + (bias[m] - rstd*mean*wrsum[m]); write fp32 Out
// =====================================================================
__device__ __forceinline__ void load_stage(
    char* smem, uint32_t sb, int c, int tid, int b, int m0, int n0, int axis,
    const unsigned short* __restrict__ apack,
    const unsigned short* __restrict__ hiP,
    const unsigned short* __restrict__ loP)
{
    const uint32_t stOff = (uint32_t)(c % NPIPE) * STAGE_BYTES;
    const uint32_t aBase = sb + stOff;
    const uint32_t bBase = aBase + A_BYTES;
    // ---- A: 128 rows x 64 bf16 (cp.async 16B) ----
    const unsigned short* ag = apack + (long)m0 * KPRIME + c * 64;
    #pragma unroll
    for (int it = 0; it < 4; it++) {
        const int flat = it * 256 + tid;
        const int m = flat >> 3, g = flat & 7;
        cp16(aBase + m * A_STRIDE + g * 16, ag + (long)m * KPRIME + g * 8);
    }
    const int kbase = (c % 6) * 64;
    const unsigned short* plane = (c < 12) ? hiP : loP;
    if (axis < 0) {
        #pragma unroll
        for (int it = 0; it < 16; it++) {
            const int flat = it * 256 + tid;
            const int k = flat >> 6, ni2 = flat & 63;
            cp4(bBase + k * B_STRIDE + ni2 * 4,
                plane + ((long)b * CH + kbase + k) * (long)S + n0 + 2 * ni2);
        }
    } else {
        // shifted sources may be 2B-aligned -> plain u16 loads
        #pragma unroll
        for (int it = 0; it < 16; it++) {
            const int flat = it * 256 + tid;
            const int k = flat >> 6, ni2 = flat & 63;
            const int ch = kbase + k;
            const int n = n0 + 2 * ni2;
            const int d = n >> 10, h = (n >> 5) & 31, w = n & 31;
            const int sh = 2 - (ch >> 7);
            int od = 1, oh = 1, ow = 1;
            if      (axis == 2) od = sh;
            else if (axis == 3) oh = sh;
            else                ow = sh;
            const unsigned short* src = plane + ((long)b * CH + ch) * (long)SPP
                        + (d + od) * PP + (h + oh) * P + (w + ow);
            const uint32_t v = (uint32_t)src[0] | ((uint32_t)src[1] << 16);
            *reinterpret_cast<uint32_t*>(smem + stOff + A_BYTES + k * B_STRIDE + ni2 * 4) = v;
        }
    }
    asm volatile("cp.async.commit_group;" ::: "memory");
}

__global__ __launch_bounds__(256, 2)
void gemm_tc(const unsigned short* __restrict__ apack,
             const unsigned short* __restrict__ hiP,
             const unsigned short* __restrict__ loP,
             float* __restrict__ Out, const float* __restrict__ bias,
             int axis, int mode,
             float* __restrict__ accOut,
             unsigned short* __restrict__ outHi, unsigned short* __restrict__ outLo,
             const float* __restrict__ stats2, const float* __restrict__ wrsum)
{
    extern __shared__ char smem[];
    const uint32_t sb = smem_u32(smem);
    const int tid = threadIdx.x, wid = tid >> 5, lane = tid & 31;
    const int m0 = blockIdx.x * 128;
    const int n0 = blockIdx.y * 128;
    const int b  = blockIdx.z;
    const int wm = (wid & 1) * 64;
    const int wn = (wid >> 1) * 32;

    float acc[4][4][4];
    #pragma unroll
    for (int i = 0; i < 4; i++)
        #pragma unroll
        for (int j = 0; j < 4; j++)
            #pragma unroll
            for (int k = 0; k < 4; k++) acc[i][j][k] = 0.f;

    load_stage(smem, sb, 0, tid, b, m0, n0, axis, apack, hiP, loP);
    load_stage(smem, sb, 1, tid, b, m0, n0, axis, apack, hiP, loP);

    for (int c = 0; c < NSTAGE; c++) {
        if (c < NSTAGE - 1)
            asm volatile("cp.async.wait_group 1;" ::: "memory");
        else
            asm volatile("cp.async.wait_group 0;" ::: "memory");
        __syncthreads();

        const uint32_t aBase = sb + (uint32_t)(c % NPIPE) * STAGE_BYTES;
        const uint32_t bBase = aBase + A_BYTES;
        #pragma unroll
        for (int ks = 0; ks < 4; ks++) {
            const int k0 = ks * 16;
            uint32_t afr[4][4], bfr[2][4];
            #pragma unroll
            for (int mt = 0; mt < 4; mt++)
                ldsm4(afr[mt], aBase + (wm + mt * 16 + (lane & 15)) * A_STRIDE
                               + (k0 + (lane >> 4) * 8) * 2);
            #pragma unroll
            for (int nt = 0; nt < 2; nt++)
                ldsm4t(bfr[nt], bBase + (k0 + (lane & 15)) * B_STRIDE
                                + (wn + nt * 16 + (lane >> 4) * 8) * 2);
            #pragma unroll
            for (int mt = 0; mt < 4; mt++)
                #pragma unroll
                for (int n8 = 0; n8 < 4; n8++)
                    mma16816(acc[mt][n8], afr[mt],
                             bfr[n8 >> 1][(n8 & 1) * 2],
                             bfr[n8 >> 1][(n8 & 1) * 2 + 1]);
        }
        if (c + 2 < NSTAGE)
            load_stage(smem, sb, c + 2, tid, b, m0, n0, axis, apack, hiP, loP);
    }

    // ---- epilogue ----
    float mean = 0.f, rstd = 1.f;
    if (mode == 4) { mean = stats2[2 * b]; rstd = stats2[2 * b + 1]; }
    float ls = 0.f, lss = 0.f;
    const int g = lane >> 2, t = lane & 3;
    #pragma unroll
    for (int mt = 0; mt < 4; mt++) {
        #pragma unroll
        for (int half = 0; half < 2; half++) {
            const int m = m0 + wm + mt * 16 + g + half * 8;
            const float bv = bias[m];
            float cc = bv;
            if (mode == 4) cc = bv - rstd * mean * wrsum[m];
            const long rowbase = ((long)b * CH + m) * (long)S + n0 + wn;
            float* op = Out + rowbase;
            #pragma unroll
            for (int n8 = 0; n8 < 4; n8++) {
                float2 v;
                if (mode == 4) {
                    v.x = rstd * acc[mt][n8][half * 2]     + cc;
                    v.y = rstd * acc[mt][n8][half * 2 + 1] + cc;
                } else {
                    v.x = acc[mt][n8][half * 2]     + bv;
                    v.y = acc[mt][n8][half * 2 + 1] + bv;
                }
                if (mode == 1 || mode == 2 || mode == 3) {
                    v.x = gelu_f(v.x); v.y = gelu_f(v.y);
                }
                const int nofs = n8 * 8 + 2 * t;
                if (mode == 2 || mode == 3) {
                    float2 o = *reinterpret_cast<const float2*>(op + nofs);
                    v.x += o.x; v.y += o.y;
                }
                if (mode == 0) {
                    ls += v.x + v.y;
                    lss = fmaf(v.x, v.x, lss); lss = fmaf(v.y, v.y, lss);
                }
                if (mode == 3) {
                    ls += v.x + v.y;
                    lss = fmaf(v.x, v.x, lss); lss = fmaf(v.y, v.y, lss);
                    unsigned short hx, lx, hy, ly;
                    split_one(v.x, hx, lx); split_one(v.y, hy, ly);
                    const long u32i = (rowbase + nofs) >> 1;
                    reinterpret_cast<uint32_t*>(outHi)[u32i] = (uint32_t)hx | ((uint32_t)hy << 16);
                    reinterpret_cast<uint32_t*>(outLo)[u32i] = (uint32_t)lx | ((uint32_t)ly << 16);
                } else {
                    *reinterpret_cast<float2*>(op + nofs) = v;
                }
            }
        }
    }
    // ---- fused stats reduction ----
    if (mode == 0 || mode == 3) {
        #pragma unroll
        for (int off = 16; off; off >>= 1) {
            ls  += __shfl_xor_sync(0xFFFFFFFFu, ls,  off);
            lss += __shfl_xor_sync(0xFFFFFFFFu, lss, off);
        }
        float* sred = reinterpret_cast<float*>(smem);
        __syncthreads();
        if (lane == 0) { sred[wid] = ls; sred[8 + wid] = lss; }
        __syncthreads();
        if (tid == 0) {
            float s = 0.f, ss = 0.f;
            #pragma unroll
            for (int i = 0; i < 8; i++) { s += sred[i]; ss += sred[8 + i]; }
            atomicAdd(&accOut[2 * b],     s);
            atomicAdd(&accOut[2 * b + 1], ss);
        }
    }
}

// ============ zero stats accumulators ============
__global__ void zero_acc()
{
    if (threadIdx.x < 2 * BATCH) { g_acc1[threadIdx.x] = 0.f; g_acc2[threadIdx.x] = 0.f; }
}

// ============ finalize stats: (sum,sumsq) -> (mean, rstd) ============
__global__ void finalize_stats(const float* __restrict__ acc, float* __restrict__ stats)
{
    const int b = threadIdx.x;
    if (b >= BATCH) return;
    const float n = (float)CH * (float)S;
    const float mean = acc[2 * b] / n;
    const float var  = acc[2 * b + 1] / n - mean * mean;
    stats[2 * b]     = mean;
    stats[2 * b + 1] = rsqrtf(var + 1e-5f);
}

// ============ pack weights: [mat][m][ hi(384) | lo(384) | hi(384) ] ============
__global__ void apack_prep(const float* __restrict__ w1, const float* __restrict__ w21,
                           const float* __restrict__ w22, const float* __restrict__ w23,
                           const float* __restrict__ w3, const float* __restrict__ g2)
{
    const int idx = blockIdx.x * blockDim.x + threadIdx.x;
    if (idx >= 5 * CH * CH) return;
    const int mat = idx / (CH * CH);
    const int rem = idx % (CH * CH);
    const int m = rem / CH, k = rem % CH;
    const float* W = (mat == 0) ? w1 : (mat == 1) ? w21 : (mat == 2) ? w22
                   : (mat == 3) ? w23 : w3;
    float v = W[m * CH + k];
    if (mat == 4) v *= g2[k];
    unsigned short hi, lo;
    split_one(v, hi, lo);
    const long base = (long)mat * AP_ELE + (long)m * KPRIME;
    g_apack[base + k]           = hi;
    g_apack[base + CH + k]      = lo;
    g_apack[base + 2 * CH + k]  = hi;
}

// ============ convert raw x -> dense hi/lo planes ============
__global__ void convert_x(const float* __restrict__ x)
{
    const long i = (long)blockIdx.x * blockDim.x + threadIdx.x;
    const long tot2 = (long)BATCH * CH * S / 2;
    if (i >= tot2) return;
    const float2 v = reinterpret_cast<const float2*>(x)[i];
    unsigned short h0, l0, h1, l1;
    split_one(v.x, h0, l0); split_one(v.y, h1, l1);
    reinterpret_cast<uint32_t*>(g_hi16)[i] = (uint32_t)h0 | ((uint32_t)h1 << 16);
    reinterpret_cast<uint32_t*>(g_lo16)[i] = (uint32_t)l0 | ((uint32_t)l1 << 16);
}

// ============ GN1 affine + GELU -> zero-padded 34^3 hi/lo planes ============
__global__ void pad_split(const float* __restrict__ g1, const float* __restrict__ bt1)
{
    const long i = (long)blockIdx.x * blockDim.x + threadIdx.x;
    if (i >= (long)BATCH * CH * SPP) return;
    const int b  = (int)(i / ((long)CH * SPP));
    const long r = i - (long)b * CH * SPP;
    const int c  = (int)(r / SPP);
    const int sp = (int)(r - (long)c * SPP);
    const int pd = sp / PP;
    const int r2 = sp - pd * PP;
    const int ph = r2 / P;
    const int pw = r2 - ph * P;
    unsigned short hi = 0, lo = 0;
    if (pd >= 1 && pd <= RR && ph >= 1 && ph <= RR && pw >= 1 && pw <= RR) {
        const int s = (pd - 1) * 1024 + (ph - 1) * RR + (pw - 1);
        float y = g_buf[((long)b * CH + c) * S + s];
        y = gelu_f((y - g_stats1[2 * b]) * g_stats1[2 * b + 1] * g1[c] + bt1[c]);
        split_one(y, hi, lo);
    }
    g_phi16[i] = hi; g_plo16[i] = lo;
}

// ====== cvec[o] = b3[o] + w3[o,:]·bt2 ; wrsum[o] = (w3·g2)[o,:]·1 ======
__global__ void cvec_kernel(const float* __restrict__ w3,
                            const float* __restrict__ bt2,
                            const float* __restrict__ b3,
                            const float* __restrict__ g2)
{
    const int o = blockIdx.x * blockDim.x + threadIdx.x;
    if (o >= CH) return;
    float s = b3[o], ws = 0.f;
    for (int c = 0; c < CH; c++) {
        s  = fmaf(w3[o * CH + c], bt2[c], s);
        ws = fmaf(w3[o * CH + c], g2[c], ws);
    }
    g_cvec[o]  = s;
    g_wrsum[o] = ws;
}

extern "C" void kernel_launch(void* const* d_in, const int* in_sizes, int n_in,
                              void* d_out, int out_size)
{
    const float* x   = (const float*)d_in[0];
    const float* w1  = (const float*)d_in[1];
    const float* b1  = (const float*)d_in[2];
    const float* g1  = (const float*)d_in[3];
    const float* bt1 = (const float*)d_in[4];
    const float* w21 = (const float*)d_in[5];
    const float* b21 = (const float*)d_in[6];
    const float* w22 = (const float*)d_in[7];
    const float* b22 = (const float*)d_in[8];
    const float* w23 = (const float*)d_in[9];
    const float* b23 = (const float*)d_in[10];
    const float* g2  = (const float*)d_in[11];
    const float* bt2 = (const float*)d_in[12];
    const float* w3  = (const float*)d_in[13];
    const float* b3  = (const float*)d_in[14];
    float* out = (float*)d_out;

    float*          buf;   cudaGetSymbolAddress((void**)&buf,   g_buf);
    unsigned short* hip;   cudaGetSymbolAddress((void**)&hip,   g_hi16);
    unsigned short* lop;   cudaGetSymbolAddress((void**)&lop,   g_lo16);
    unsigned short* phip;  cudaGetSymbolAddress((void**)&phip,  g_phi16);
    unsigned short* plop;  cudaGetSymbolAddress((void**)&plop,  g_plo16);
    unsigned short* apk;   cudaGetSymbolAddress((void**)&apk,   g_apack);
    float*          cvec;  cudaGetSymbolAddress((void**)&cvec,  g_cvec);
    float*          wrs;   cudaGetSymbolAddress((void**)&wrs,   g_wrsum);
    float*          acc1;  cudaGetSymbolAddress((void**)&acc1,  g_acc1);
    float*          acc2;  cudaGetSymbolAddress((void**)&acc2,  g_acc2);
    float*          st1;   cudaGetSymbolAddress((void**)&st1,   g_stats1);
    float*          st2;   cudaGetSymbolAddress((void**)&st2,   g_stats2);

    cudaFuncSetAttribute(gemm_tc, cudaFuncAttributeMaxDynamicSharedMemorySize, SMEM_GEMM);

    const dim3 gg(3, S / 128, BATCH);   // m fastest -> L2 reuse of B across m-tiles

    // 0) zero accumulators; pack weights; fold biases; convert x
    zero_acc<<<1, 32>>>();
    apack_prep<<<(5 * CH * CH + 255) / 256, 256>>>(w1, w21, w22, w23, w3, g2);
    cvec_kernel<<<2, 192>>>(w3, bt2, b3, g2);
    {
        const long tot2 = (long)BATCH * CH * S / 2;
        convert_x<<<(unsigned)((tot2 + 255) / 256), 256>>>(x);
    }
    // 1) conv1 (mode 0: + fused GN1 stats)
    gemm_tc<<<gg, 256, SMEM_GEMM>>>(apk + 0L * AP_ELE, hip, lop, buf, b1, -1, 0,
                                    acc1, nullptr, nullptr, nullptr, nullptr);
    finalize_stats<<<1, 32>>>(acc1, st1);
    // 2) GN1 affine + GELU + zero-padded hi/lo planes
    {
        const long tot = (long)BATCH * CH * SPP;
        pad_split<<<(unsigned)((tot + 255) / 256), 256>>>(g1, bt1);
    }
    // 3) three shifted branch convs; last one fuses GN2 stats + hi/lo write
    gemm_tc<<<gg, 256, SMEM_GEMM>>>(apk + 1L * AP_ELE, phip, plop, buf, b21, 3, 1,
                                    nullptr, nullptr, nullptr, nullptr, nullptr);
    gemm_tc<<<gg, 256, SMEM_GEMM>>>(apk + 2L * AP_ELE, phip, plop, buf, b22, 2, 2,
                                    nullptr, nullptr, nullptr, nullptr, nullptr);
    gemm_tc<<<gg, 256, SMEM_GEMM>>>(apk + 3L * AP_ELE, phip, plop, buf, b23, 4, 3,
                                    acc2, hip, lop, nullptr, nullptr);
    finalize_stats<<<1, 32>>>(acc2, st2);
    // 4) final conv on raw planes; GN2 folded via rstd scale + rowsum correction
    gemm_tc<<<gg, 256, SMEM_GEMM>>>(apk + 4L * AP_ELE, hip, lop, out, cvec, -1, 4,
                                    nullptr, nullptr, nullptr, st2, wrs);
}